// round 1
// baseline (speedup 1.0000x reference)
#include <cuda_runtime.h>
#include <math.h>

// Problem constants
#define BATCH 16
#define CIN   256
#define HH    56
#define WW    56
#define COUT  256
#define NEXP  8
#define KVOL  2304            // CIN * 3 * 3
#define WPERB 589824          // COUT * CIN * 3 * 3

// Conv tiling
#define OCT 64                // output channels per block
#define TH  8                 // output rows per block
#define TW  28                // output cols per block
#define CC  8                 // cin chunk per mainloop iter

// Scratch (no cudaMalloc allowed)
__device__ float g_pooled[BATCH * CIN];
__device__ float g_r[BATCH * NEXP];
__device__ float g_cw[(size_t)BATCH * WPERB];   // 37.75 MB combined weights

// ---------------------------------------------------------------------------
// Kernel 1: global average pool  x[b,c,:,:] -> g_pooled[b*CIN+c]
// ---------------------------------------------------------------------------
__global__ void pool_kernel(const float* __restrict__ x) {
    int bc = blockIdx.x;                       // 0 .. BATCH*CIN-1
    const float* p = x + (size_t)bc * (HH * WW);
    float s = 0.f;
    for (int i = threadIdx.x; i < HH * WW; i += 128) s += p[i];
    // warp reduce
    #pragma unroll
    for (int o = 16; o > 0; o >>= 1) s += __shfl_down_sync(0xffffffffu, s, o);
    __shared__ float red[4];
    if ((threadIdx.x & 31) == 0) red[threadIdx.x >> 5] = s;
    __syncthreads();
    if (threadIdx.x == 0)
        g_pooled[bc] = (red[0] + red[1] + red[2] + red[3]) * (1.0f / (HH * WW));
}

// ---------------------------------------------------------------------------
// Kernel 2: routing  r[b,e] = sigmoid(pooled[b,:] . rw[e,:] + rb[e])
// ---------------------------------------------------------------------------
__global__ void route_kernel(const float* __restrict__ rw,
                             const float* __restrict__ rb) {
    int t = threadIdx.x;                       // 0..127 = (b,e) pairs
    int b = t >> 3, e = t & 7;
    const float* p = g_pooled + b * CIN;
    const float* w = rw + e * CIN;
    float a = rb[e];
    for (int c = 0; c < CIN; c++) a += p[c] * w[c];
    g_r[t] = 1.0f / (1.0f + __expf(-a));
}

// ---------------------------------------------------------------------------
// Kernel 3: combined weights  cw[b,j] = sum_e r[b,e] * W[e,j]
// Each thread owns one weight position j for ALL 16 samples (reads the 8
// expert values once -> 16 outputs).
// ---------------------------------------------------------------------------
__global__ void combine_kernel(const float* __restrict__ kw) {
    __shared__ float rs[BATCH * NEXP];
    if (threadIdx.x < BATCH * NEXP) rs[threadIdx.x] = g_r[threadIdx.x];
    __syncthreads();
    int j = blockIdx.x * blockDim.x + threadIdx.x;
    if (j >= WPERB) return;
    float wv[NEXP];
    #pragma unroll
    for (int e = 0; e < NEXP; e++) wv[e] = kw[(size_t)e * WPERB + j];
    #pragma unroll
    for (int b = 0; b < BATCH; b++) {
        float a = 0.f;
        #pragma unroll
        for (int e = 0; e < NEXP; e++) a += rs[b * NEXP + e] * wv[e];
        g_cw[(size_t)b * WPERB + j] = a;
    }
}

// ---------------------------------------------------------------------------
// Kernel 4: per-sample 3x3 conv (pad 1) + BN + SiLU
// Block: 64 oc x (8 x 28) spatial for one sample. 256 threads.
// Thread microtile: 8 oc x 7 spatial (spatial strided by 32 for coalescing).
// Mainloop over cin in chunks of 8, staged in SMEM.
// ---------------------------------------------------------------------------
__global__ __launch_bounds__(256, 2)
void conv_kernel(const float* __restrict__ x,
                 const float* __restrict__ bn_gamma,
                 const float* __restrict__ bn_beta,
                 const float* __restrict__ bn_mean,
                 const float* __restrict__ bn_var,
                 float* __restrict__ out) {
    __shared__ float xs[CC][TH + 2][TW + 4];   // [8][10][32], cols 30..31 unused
    __shared__ float ws[OCT][CC * 9];          // [64][72], matches global layout

    const int tid = threadIdx.x;
    const int tx = tid & 31;                   // spatial lane
    const int ty = tid >> 5;                   // oc group (8 groups of 8 oc)

    const int b       = blockIdx.z;
    const int ocBase  = blockIdx.y * OCT;
    const int rowBase = (blockIdx.x >> 1) * TH;
    const int colBase = (blockIdx.x & 1) * TW;

    // Per-thread spatial microtile coordinates (within the 8x28 tile)
    int rj[7], cj[7];
    #pragma unroll
    for (int j = 0; j < 7; j++) {
        int s = tx + 32 * j;                   // 0..223
        rj[j] = s / TW;
        cj[j] = s % TW;
    }

    float acc[8][7];
    #pragma unroll
    for (int o = 0; o < 8; o++)
        #pragma unroll
        for (int j = 0; j < 7; j++) acc[o][j] = 0.f;

    const float* xb  = x + (size_t)b * CIN * (HH * WW);
    const float* cwb = g_cw + (size_t)b * WPERB + (size_t)ocBase * KVOL;

    for (int cb = 0; cb < CIN; cb += CC) {
        __syncthreads();
        // Stage input tile (+halo) for CC channels, zero-padded at borders
        for (int i = tid; i < CC * (TH + 2) * (TW + 2); i += 256) {
            int ci  = i / ((TH + 2) * (TW + 2));
            int rem = i % ((TH + 2) * (TW + 2));
            int rr  = rem / (TW + 2);
            int cc  = rem % (TW + 2);
            int gr = rowBase - 1 + rr;
            int gc = colBase - 1 + cc;
            float v = 0.f;
            if (gr >= 0 && gr < HH && gc >= 0 && gc < WW)
                v = xb[(size_t)(cb + ci) * (HH * WW) + gr * WW + gc];
            xs[ci][rr][cc] = v;
        }
        // Stage combined weights: 64 oc x 72 (cc*9) contiguous runs
        const float* cwp = cwb + (size_t)cb * 9;
        for (int i = tid; i < OCT * CC * 9; i += 256) {   // exactly 18 iters
            int oc = i / 72;
            int kj = i % 72;
            ws[oc][kj] = cwp[(size_t)oc * KVOL + kj];
        }
        __syncthreads();

        #pragma unroll 2
        for (int ci = 0; ci < CC; ci++) {
            #pragma unroll
            for (int kh = 0; kh < 3; kh++) {
                #pragma unroll
                for (int kw = 0; kw < 3; kw++) {
                    float wv[8];
                    #pragma unroll
                    for (int o = 0; o < 8; o++)        // warp-broadcast LDS
                        wv[o] = ws[ty * 8 + o][ci * 9 + kh * 3 + kw];
                    float xv[7];
                    #pragma unroll
                    for (int j = 0; j < 7; j++)
                        xv[j] = xs[ci][rj[j] + kh][cj[j] + kw];
                    #pragma unroll
                    for (int o = 0; o < 8; o++)
                        #pragma unroll
                        for (int j = 0; j < 7; j++)
                            acc[o][j] += wv[o] * xv[j];
                }
            }
        }
    }

    // Epilogue: BN (inference) + SiLU, then store
    float* ob = out + (size_t)b * COUT * (HH * WW);
    #pragma unroll
    for (int o = 0; o < 8; o++) {
        int oc = ocBase + ty * 8 + o;
        float inv = bn_gamma[oc] * rsqrtf(bn_var[oc] + 1e-5f);
        float bia = bn_beta[oc] - bn_mean[oc] * inv;
        float* op = ob + (size_t)oc * (HH * WW);
        #pragma unroll
        for (int j = 0; j < 7; j++) {
            float z = acc[o][j] * inv + bia;
            float sig = 1.0f / (1.0f + __expf(-z));
            op[(rowBase + rj[j]) * WW + (colBase + cj[j])] = z * sig;
        }
    }
}

// ---------------------------------------------------------------------------
extern "C" void kernel_launch(void* const* d_in, const int* in_sizes, int n_in,
                              void* d_out, int out_size) {
    const float* x         = (const float*)d_in[0];
    const float* routing_w = (const float*)d_in[1];
    const float* routing_b = (const float*)d_in[2];
    const float* kernel_w  = (const float*)d_in[3];
    const float* bn_gamma  = (const float*)d_in[4];
    const float* bn_beta   = (const float*)d_in[5];
    const float* bn_mean   = (const float*)d_in[6];
    const float* bn_var    = (const float*)d_in[7];
    float* out = (float*)d_out;

    pool_kernel<<<BATCH * CIN, 128>>>(x);
    route_kernel<<<1, 128>>>(routing_w, routing_b);
    combine_kernel<<<(WPERB + 255) / 256, 256>>>(kernel_w);

    dim3 grid(14 /* 7 row x 2 col tiles */, COUT / OCT, BATCH);
    conv_kernel<<<grid, 256>>>(x, bn_gamma, bn_beta, bn_mean, bn_var, out);
}

// round 6
// speedup vs baseline: 5.0982x; 5.0982x over previous
#include <cuda_runtime.h>
#include <cuda_fp16.h>
#include <cstdint>
#include <math.h>

// ---------------------------------------------------------------------------
// Problem constants
// ---------------------------------------------------------------------------
#define BATCH 16
#define CIN   256
#define COUT  256
#define HH    56
#define WW    56
#define HWSZ  3136
#define NEXP  8
#define KTOT  2304          // 9 * 256, reordered k' = kpos*256 + ci
#define PROW  58            // padded row width
#define PPAD  64            // leading guard rows in pimg
#define PTOT  3712          // guard + 58*58 + tail guard
#define NCH   36            // K chunks of 64
#define NT    27            // N tiles of 128 over 3364 padded px

// ---------------------------------------------------------------------------
// Global scratch (no cudaMalloc allowed; __device__ globals are zero-init)
// ---------------------------------------------------------------------------
__device__ float g_pooled[BATCH * CIN];
__device__ float g_r[BATCH * NEXP];
__device__ __half g_pimg[(size_t)BATCH * PTOT * CIN];
__device__ __half g_cw[(size_t)BATCH * COUT * KTOT];

// ---------------------------------------------------------------------------
// Helpers (portable PTX only: sm_80-class features, safe at compute_103)
// ---------------------------------------------------------------------------
#define SWZ(o) ((o) ^ (((o) >> 3) & 0x70))

static __device__ __forceinline__ uint32_t smem_u32(const void* p) {
    uint32_t a;
    asm("{ .reg .u64 t; cvta.to.shared.u64 t, %1; cvt.u32.u64 %0, t; }"
        : "=r"(a) : "l"(p));
    return a;
}

static __device__ __forceinline__ void cp16(uint32_t dst, const void* src) {
    size_t g = __cvta_generic_to_global(src);
    asm volatile("cp.async.cg.shared.global [%0], [%1], 16;"
                 :: "r"(dst), "l"(g) : "memory");
}
#define CP_COMMIT() asm volatile("cp.async.commit_group;" ::: "memory")
#define CP_WAIT1()  asm volatile("cp.async.wait_group 1;" ::: "memory")
#define CP_WAIT0()  asm volatile("cp.async.wait_group 0;" ::: "memory")

static __device__ __forceinline__ void ldmx4(uint32_t* r, uint32_t addr) {
    asm volatile("ldmatrix.sync.aligned.m8n8.x4.shared.b16 {%0,%1,%2,%3}, [%4];"
                 : "=r"(r[0]), "=r"(r[1]), "=r"(r[2]), "=r"(r[3]) : "r"(addr));
}

static __device__ __forceinline__ void mma16816(float* d, const uint32_t* a,
                                                uint32_t b0, uint32_t b1) {
    asm volatile(
        "mma.sync.aligned.m16n8k16.row.col.f32.f16.f16.f32 "
        "{%0,%1,%2,%3}, {%4,%5,%6,%7}, {%8,%9}, {%0,%1,%2,%3};"
        : "+f"(d[0]), "+f"(d[1]), "+f"(d[2]), "+f"(d[3])
        : "r"(a[0]), "r"(a[1]), "r"(a[2]), "r"(a[3]), "r"(b0), "r"(b1));
}

// ---------------------------------------------------------------------------
// Kernel 1: global average pool
// ---------------------------------------------------------------------------
__global__ void pool_kernel(const float* __restrict__ x) {
    int bc = blockIdx.x;
    const float* p = x + (size_t)bc * HWSZ;
    float s = 0.f;
    for (int i = threadIdx.x; i < HWSZ; i += 128) s += p[i];
    #pragma unroll
    for (int o = 16; o > 0; o >>= 1) s += __shfl_down_sync(0xffffffffu, s, o);
    __shared__ float red[4];
    if ((threadIdx.x & 31) == 0) red[threadIdx.x >> 5] = s;
    __syncthreads();
    if (threadIdx.x == 0)
        g_pooled[bc] = (red[0] + red[1] + red[2] + red[3]) * (1.0f / HWSZ);
}

// ---------------------------------------------------------------------------
// Kernel 2: routing
// ---------------------------------------------------------------------------
__global__ void route_kernel(const float* __restrict__ rw,
                             const float* __restrict__ rb) {
    int t = threadIdx.x;
    int b = t >> 3, e = t & 7;
    const float* p = g_pooled + b * CIN;
    const float* w = rw + e * CIN;
    float a = rb[e];
    for (int c = 0; c < CIN; c++) a += p[c] * w[c];
    g_r[t] = 1.0f / (1.0f + __expf(-a));
}

// ---------------------------------------------------------------------------
// Kernel 3: combined weights, K-reordered (k' = kpos*256 + ci), fp16.
// grid = 256 (oc), block = 256 (ci)
// ---------------------------------------------------------------------------
__global__ void combine_kernel(const float* __restrict__ kw) {
    __shared__ float rs[BATCH * NEXP];
    if (threadIdx.x < BATCH * NEXP) rs[threadIdx.x] = g_r[threadIdx.x];
    __syncthreads();
    int oc = blockIdx.x, ci = threadIdx.x;
    float wv[NEXP][9];
    #pragma unroll
    for (int e = 0; e < NEXP; e++) {
        const float* p = kw + ((size_t)(e * COUT + oc) * CIN + ci) * 9;
        #pragma unroll
        for (int j = 0; j < 9; j++) wv[e][j] = p[j];
    }
    for (int b = 0; b < BATCH; b++) {
        float a[9];
        #pragma unroll
        for (int j = 0; j < 9; j++) a[j] = 0.f;
        #pragma unroll
        for (int e = 0; e < NEXP; e++) {
            float r = rs[b * NEXP + e];
            #pragma unroll
            for (int j = 0; j < 9; j++) a[j] += r * wv[e][j];
        }
        size_t base = (size_t)(b * COUT + oc) * KTOT;
        #pragma unroll
        for (int j = 0; j < 9; j++)
            g_cw[base + j * 256 + ci] = __float2half_rn(a[j]);
    }
}

// ---------------------------------------------------------------------------
// Kernel 4: padded + transposed image  pimg[b][pos][ci] (fp16)
// pos = PPAD + (r+1)*58 + (w+1); zeros elsewhere (pad cols/rows + guards).
// grid = (58 pos-tiles of 64, 4 ci-tiles of 64, 16 b), block 256
// ---------------------------------------------------------------------------
__global__ void prep_kernel(const float* __restrict__ x) {
    __shared__ float tile[64][65];
    int b = blockIdx.z, ciB = blockIdx.y * 64, posB = blockIdx.x * 64;
    int tid = threadIdx.x;
    for (int i = tid; i < 64 * 64; i += 256) {
        int ci_l = i >> 6, pos_l = i & 63;
        int p = posB + pos_l - PPAD;
        float v = 0.f;
        if (p >= 0) {
            int r = p / PROW - 1, w = p % PROW - 1;
            if (r >= 0 && r < HH && w >= 0 && w < WW)
                v = x[((size_t)(b * CIN + ciB + ci_l)) * HWSZ + r * WW + w];
        }
        tile[ci_l][pos_l] = v;
    }
    __syncthreads();
    for (int i = tid; i < 64 * 64; i += 256) {
        int pos_l = i >> 6, ci_l = i & 63;
        g_pimg[((size_t)b * PTOT + posB + pos_l) * CIN + ciB + ci_l] =
            __float2half_rn(tile[ci_l][pos_l]);
    }
}

// ---------------------------------------------------------------------------
// Kernel 5: fp16 mma.sync implicit-GEMM conv + BN + SiLU
// grid = (27 ntiles, 2 mtiles, 16 b), block 256 (8 warps, 2x4), 64KB dyn smem
// Tile: M128 x N128, BK=64.  Warp tile: 64 x 32.
// ---------------------------------------------------------------------------
#define STG 32768           // stage stride bytes (A 16KB + B 16KB)
#define AOFF 0
#define BOFF 16384
#define SMEM_DYN (2 * STG)

extern __shared__ char smem_raw[];

__global__ __launch_bounds__(256, 2)
void conv_hmma_kernel(const float* __restrict__ bn_gamma,
                      const float* __restrict__ bn_beta,
                      const float* __restrict__ bn_mean,
                      const float* __restrict__ bn_var,
                      float* __restrict__ out) {
    const int tid  = threadIdx.x;
    const int lane = tid & 31;
    const int wid  = tid >> 5;
    const int wm   = wid & 1;          // warp row (0..1) -> 64 oc
    const int wn   = wid >> 1;         // warp col (0..3) -> 32 px
    const int p0   = blockIdx.x * 128;
    const int mt   = blockIdx.y;
    const int b    = blockIdx.z;

    const uint32_t sb = smem_u32(smem_raw);

    // staging: thread loads 4 A segs + 4 B segs (16B each)
    const int srow = tid >> 1;               // 0..127
    const int scol = (tid & 1) * 4;          // seg base 0 or 4
    const __half* cwrow = g_cw + (size_t)(b * COUT + mt * 128 + srow) * KTOT;

    auto stage = [&](int it, uint32_t stb) {
        int kpos = it >> 2;
        int ciB  = (it & 3) << 6;
        int off  = (kpos / 3) * PROW + (kpos % 3) - (PROW + 1);
        const __half* ga = cwrow + it * 64 + scol * 8;
        const __half* gb = g_pimg +
            ((size_t)b * PTOT + PPAD + p0 + off + srow) * CIN + ciB + scol * 8;
        uint32_t abase = stb + AOFF, bbase = stb + BOFF;
        uint32_t so = srow * 128 + scol * 16;
        #pragma unroll
        for (int i = 0; i < 4; i++) {
            cp16(abase + SWZ(so + i * 16), ga + i * 8);
            cp16(bbase + SWZ(so + i * 16), gb + i * 8);
        }
        CP_COMMIT();
    };

    float d[4][4][4];
    #pragma unroll
    for (int im = 0; im < 4; im++)
        #pragma unroll
        for (int in = 0; in < 4; in++)
            #pragma unroll
            for (int e = 0; e < 4; e++) d[im][in][e] = 0.f;

    // per-lane ldmatrix address pieces
    const int a_row = lane & 15;             // row within 16
    const int a_kh  = (lane >> 4) * 8;       // k half offset
    const int b_mi  = lane >> 3;             // matrix index 0..3
    const int b_row = ((b_mi >> 1) << 3) + (lane & 7);  // n within 16
    const int b_kh  = (b_mi & 1) * 8;

    stage(0, sb);

    for (int it = 0; it < NCH; it++) {
        if (it + 1 < NCH) stage(it + 1, sb + ((it + 1) & 1) * STG);
        if (it + 1 < NCH) { CP_WAIT1(); } else { CP_WAIT0(); }
        __syncthreads();

        uint32_t as = sb + (it & 1) * STG + AOFF;
        uint32_t bs = sb + (it & 1) * STG + BOFF;

        #pragma unroll
        for (int kk = 0; kk < 4; kk++) {
            uint32_t a[4][4];
            #pragma unroll
            for (int im = 0; im < 4; im++) {
                uint32_t byte = (wm * 64 + im * 16 + a_row) * 128 +
                                (kk * 16 + a_kh) * 2;
                ldmx4(a[im], as + SWZ(byte));
            }
            uint32_t bf[2][4];
            #pragma unroll
            for (int j = 0; j < 2; j++) {
                uint32_t byte = (wn * 32 + j * 16 + b_row) * 128 +
                                (kk * 16 + b_kh) * 2;
                ldmx4(bf[j], bs + SWZ(byte));
            }
            #pragma unroll
            for (int im = 0; im < 4; im++)
                #pragma unroll
                for (int in = 0; in < 4; in++)
                    mma16816(d[im][in], a[im],
                             bf[in >> 1][(in & 1) * 2],
                             bf[in >> 1][(in & 1) * 2 + 1]);
        }
        __syncthreads();
    }

    // ---- epilogue: BN + SiLU + masked store ----
    const int t4 = lane >> 2, tp = lane & 3;
    #pragma unroll
    for (int im = 0; im < 4; im++) {
        int mloc = wm * 64 + im * 16 + t4;
        #pragma unroll
        for (int h = 0; h < 2; h++) {
            int oc = mt * 128 + mloc + h * 8;
            float inv = bn_gamma[oc] * rsqrtf(bn_var[oc] + 1e-5f);
            float bia = bn_beta[oc] - bn_mean[oc] * inv;
            float* ob = out + (size_t)(b * COUT + oc) * HWSZ;
            #pragma unroll
            for (int in = 0; in < 4; in++) {
                int pbase = p0 + wn * 32 + in * 8 + tp * 2;
                #pragma unroll
                for (int e = 0; e < 2; e++) {
                    int p = pbase + e;
                    int rr = p / PROW - 1, ww = p % PROW - 1;
                    if (rr >= 0 && rr < HH && ww >= 0 && ww < WW) {
                        float z = d[im][in][h * 2 + e] * inv + bia;
                        ob[rr * WW + ww] = z / (1.f + __expf(-z));
                    }
                }
            }
        }
    }
}

// ---------------------------------------------------------------------------
extern "C" void kernel_launch(void* const* d_in, const int* in_sizes, int n_in,
                              void* d_out, int out_size) {
    const float* x         = (const float*)d_in[0];
    const float* routing_w = (const float*)d_in[1];
    const float* routing_b = (const float*)d_in[2];
    const float* kernel_w  = (const float*)d_in[3];
    const float* bn_gamma  = (const float*)d_in[4];
    const float* bn_beta   = (const float*)d_in[5];
    const float* bn_mean   = (const float*)d_in[6];
    const float* bn_var    = (const float*)d_in[7];
    float* out = (float*)d_out;

    cudaFuncSetAttribute(conv_hmma_kernel,
                         cudaFuncAttributeMaxDynamicSharedMemorySize, SMEM_DYN);

    pool_kernel<<<BATCH * CIN, 128>>>(x);
    route_kernel<<<1, 128>>>(routing_w, routing_b);
    combine_kernel<<<COUT, 256>>>(kernel_w);
    prep_kernel<<<dim3(PTOT / 64, CIN / 64, BATCH), 256>>>(x);

    dim3 grid(NT, 2, BATCH);
    conv_hmma_kernel<<<grid, 256, SMEM_DYN>>>(bn_gamma, bn_beta, bn_mean,
                                              bn_var, out);
}

// round 12
// speedup vs baseline: 5.5321x; 1.0851x over previous
#include <cuda_runtime.h>
#include <cuda_fp16.h>
#include <cstdint>
#include <math.h>

// ---------------------------------------------------------------------------
// Problem constants
// ---------------------------------------------------------------------------
#define BATCH 16
#define CIN   256
#define COUT  256
#define HH    56
#define WW    56
#define HWSZ  3136
#define NEXP  8
#define KTOT  2304          // 9 * 256, reordered k' = kpos*256 + ci
#define PROW  58            // padded row width
#define PPAD  64            // leading guard rows in pimg
#define PTOT  3712          // guard + 58*58 + tail guard
#define NCH   36            // K chunks of 64
#define NT    27            // N tiles of 128 over 3364 padded px

// ---------------------------------------------------------------------------
// Global scratch (no cudaMalloc allowed; __device__ globals are zero-init)
// ---------------------------------------------------------------------------
__device__ float g_pooled[BATCH * CIN];
__device__ float g_r[BATCH * NEXP];
__device__ __half g_pimg[(size_t)BATCH * PTOT * CIN];
__device__ __half g_cw[(size_t)BATCH * COUT * KTOT];

// ---------------------------------------------------------------------------
// Helpers (portable PTX only: sm_80-class features, safe at compute_103)
// ---------------------------------------------------------------------------
#define SWZ(o) ((o) ^ (((o) >> 3) & 0x70))

static __device__ __forceinline__ uint32_t smem_u32(const void* p) {
    uint32_t a;
    asm("{ .reg .u64 t; cvta.to.shared.u64 t, %1; cvt.u32.u64 %0, t; }"
        : "=r"(a) : "l"(p));
    return a;
}

static __device__ __forceinline__ void cp16(uint32_t dst, const void* src) {
    size_t g = __cvta_generic_to_global(src);
    asm volatile("cp.async.cg.shared.global [%0], [%1], 16;"
                 :: "r"(dst), "l"(g) : "memory");
}
#define CP_COMMIT() asm volatile("cp.async.commit_group;" ::: "memory")
#define CP_WAIT1()  asm volatile("cp.async.wait_group 1;" ::: "memory")
#define CP_WAIT0()  asm volatile("cp.async.wait_group 0;" ::: "memory")

static __device__ __forceinline__ void ldmx4(uint32_t* r, uint32_t addr) {
    asm volatile("ldmatrix.sync.aligned.m8n8.x4.shared.b16 {%0,%1,%2,%3}, [%4];"
                 : "=r"(r[0]), "=r"(r[1]), "=r"(r[2]), "=r"(r[3]) : "r"(addr));
}

static __device__ __forceinline__ void mma16816(float* d, const uint32_t* a,
                                                uint32_t b0, uint32_t b1) {
    asm volatile(
        "mma.sync.aligned.m16n8k16.row.col.f32.f16.f16.f32 "
        "{%0,%1,%2,%3}, {%4,%5,%6,%7}, {%8,%9}, {%0,%1,%2,%3};"
        : "+f"(d[0]), "+f"(d[1]), "+f"(d[2]), "+f"(d[3])
        : "r"(a[0]), "r"(a[1]), "r"(a[2]), "r"(a[3]), "r"(b0), "r"(b1));
}

// ---------------------------------------------------------------------------
// Kernel 1: global average pool (float4 vectorized)
// ---------------------------------------------------------------------------
__global__ void pool_kernel(const float* __restrict__ x) {
    int bc = blockIdx.x;
    const float4* p = (const float4*)(x + (size_t)bc * HWSZ);
    float s = 0.f;
    for (int i = threadIdx.x; i < HWSZ / 4; i += 128) {
        float4 v = p[i];
        s += (v.x + v.y) + (v.z + v.w);
    }
    #pragma unroll
    for (int o = 16; o > 0; o >>= 1) s += __shfl_down_sync(0xffffffffu, s, o);
    __shared__ float red[4];
    if ((threadIdx.x & 31) == 0) red[threadIdx.x >> 5] = s;
    __syncthreads();
    if (threadIdx.x == 0)
        g_pooled[bc] = (red[0] + red[1] + red[2] + red[3]) * (1.0f / HWSZ);
}

// ---------------------------------------------------------------------------
// Kernel 2: routing
// ---------------------------------------------------------------------------
__global__ void route_kernel(const float* __restrict__ rw,
                             const float* __restrict__ rb) {
    int t = threadIdx.x;
    int b = t >> 3, e = t & 7;
    const float* p = g_pooled + b * CIN;
    const float* w = rw + e * CIN;
    float a = rb[e];
    for (int c = 0; c < CIN; c++) a += p[c] * w[c];
    g_r[t] = 1.0f / (1.0f + __expf(-a));
}

// ---------------------------------------------------------------------------
// Kernel 3: combined weights, K-reordered (k' = kpos*256 + ci), fp16.
// ---------------------------------------------------------------------------
__global__ void combine_kernel(const float* __restrict__ kw) {
    __shared__ float rs[BATCH * NEXP];
    if (threadIdx.x < BATCH * NEXP) rs[threadIdx.x] = g_r[threadIdx.x];
    __syncthreads();
    int oc = blockIdx.x, ci = threadIdx.x;
    float wv[NEXP][9];
    #pragma unroll
    for (int e = 0; e < NEXP; e++) {
        const float* p = kw + ((size_t)(e * COUT + oc) * CIN + ci) * 9;
        #pragma unroll
        for (int j = 0; j < 9; j++) wv[e][j] = p[j];
    }
    for (int b = 0; b < BATCH; b++) {
        float a[9];
        #pragma unroll
        for (int j = 0; j < 9; j++) a[j] = 0.f;
        #pragma unroll
        for (int e = 0; e < NEXP; e++) {
            float r = rs[b * NEXP + e];
            #pragma unroll
            for (int j = 0; j < 9; j++) a[j] += r * wv[e][j];
        }
        size_t base = (size_t)(b * COUT + oc) * KTOT;
        #pragma unroll
        for (int j = 0; j < 9; j++)
            g_cw[base + j * 256 + ci] = __float2half_rn(a[j]);
    }
}

// ---------------------------------------------------------------------------
// Kernel 4: padded + transposed image  pimg[b][pos][ci] (fp16)
// pos = PPAD + (r+1)*58 + (w+1); zeros elsewhere. LUT kills the div/mod.
// grid = (58 pos-tiles of 64, 4 ci-tiles of 64, 16 b), block 256
// ---------------------------------------------------------------------------
__global__ void prep_kernel(const float* __restrict__ x) {
    __shared__ float tile[64][65];
    __shared__ int s_off[64];                 // x-plane offset or -1
    int b = blockIdx.z, ciB = blockIdx.y * 64, posB = blockIdx.x * 64;
    int tid = threadIdx.x;
    if (tid < 64) {
        int p = posB + tid - PPAD;
        int off = -1;
        if (p >= 0) {
            int r = p / PROW - 1, w = p % PROW - 1;
            if (r >= 0 && r < HH && w >= 0 && w < WW) off = r * WW + w;
        }
        s_off[tid] = off;
    }
    __syncthreads();
    for (int i = tid; i < 64 * 64; i += 256) {
        int ci_l = i >> 6, pos_l = i & 63;
        int off = s_off[pos_l];
        tile[ci_l][pos_l] = (off >= 0)
            ? x[((size_t)(b * CIN + ciB + ci_l)) * HWSZ + off] : 0.f;
    }
    __syncthreads();
    // half2 writes: 64 pos x 32 ci-pairs
    for (int i = tid; i < 64 * 32; i += 256) {
        int pos_l = i >> 5, cp = i & 31;
        __half2 v = __floats2half2_rn(tile[cp * 2][pos_l], tile[cp * 2 + 1][pos_l]);
        *(__half2*)(g_pimg + ((size_t)b * PTOT + posB + pos_l) * CIN + ciB + cp * 2) = v;
    }
}

// ---------------------------------------------------------------------------
// Kernel 5: fp16 mma.sync implicit-GEMM conv + BN + SiLU
// grid = (27 ntiles, 16 b), block 512 (16 warps, 4x4), 192KB dyn smem
// Tile: M256 x N128, BK=64. Warp tile: 64x32.
// B is staged ONCE as a 256-row x 256-ci pixel window (shifted views give all
// 9 kpos B-tiles); A double-buffered 32KB chunks.
// ---------------------------------------------------------------------------
#define ASTG 32768                 // one A stage (256 rows x 128B)
#define BWIN_OFF (2 * ASTG)        // B window offset
#define SMEM_DYN (2 * ASTG + 131072)

extern __shared__ char smem_raw[];

__global__ __launch_bounds__(512, 1)
void conv_hmma_kernel(const float* __restrict__ bn_gamma,
                      const float* __restrict__ bn_beta,
                      const float* __restrict__ bn_mean,
                      const float* __restrict__ bn_var,
                      float* __restrict__ out) {
    const int tid  = threadIdx.x;
    const int lane = tid & 31;
    const int wid  = tid >> 5;
    const int wm   = wid & 3;          // warp row (0..3) -> 64 oc
    const int wn   = wid >> 2;         // warp col (0..3) -> 32 px
    const int p0   = blockIdx.x * 128;
    const int b    = blockIdx.y;

    const uint32_t sb = smem_u32(smem_raw);
    const uint32_t bw = sb + BWIN_OFF;

    // ---- B window staging: rows p0-59 .. p0+196 (256 rows x 512B) ----
    // store 16B chunk c of row r at column (c ^ (r&7))
    {
        const __half* gp = g_pimg + ((size_t)b * PTOT + PPAD + p0 - 59) * CIN;
        #pragma unroll
        for (int i = 0; i < 16; i++) {
            int idx = i * 512 + tid;
            int r = idx >> 5, c = idx & 31;
            cp16(bw + r * 512 + (((uint32_t)(c ^ (r & 7))) << 4),
                 gp + (size_t)r * CIN + c * 8);
        }
        CP_COMMIT();
    }

    // ---- A staging: 256 rows x 64 ci (128B rows, SW128 swizzle) ----
    const int srow = tid >> 1;               // 0..255
    const int scol = (tid & 1) * 4;          // 16B seg base 0 or 4
    const __half* cwrow = g_cw + (size_t)(b * COUT + srow) * KTOT;

    auto stageA = [&](int it, uint32_t stb) {
        const __half* ga = cwrow + it * 64 + scol * 8;
        uint32_t so = srow * 128 + scol * 16;
        #pragma unroll
        for (int i = 0; i < 4; i++)
            cp16(stb + SWZ(so + i * 16), ga + i * 8);
        CP_COMMIT();
    };

    float d[4][4][4];
    #pragma unroll
    for (int im = 0; im < 4; im++)
        #pragma unroll
        for (int in = 0; in < 4; in++)
            #pragma unroll
            for (int e = 0; e < 4; e++) d[im][in][e] = 0.f;

    // per-lane ldmatrix address pieces
    const int a_row = lane & 15;
    const int a_kh  = (lane >> 4) * 8;
    const int b_mi  = lane >> 3;                         // matrix 0..3
    const int b_row = ((b_mi >> 1) << 3) + (lane & 7);   // n within 16
    const int b_ck  = b_mi & 1;                          // k-half chunk

    stageA(0, sb);

    for (int it = 0; it < NCH; it++) {
        if (it + 1 < NCH) stageA(it + 1, sb + ((it + 1) & 1) * ASTG);
        if (it + 1 < NCH) { CP_WAIT1(); } else { CP_WAIT0(); }
        __syncthreads();

        uint32_t as = sb + (it & 1) * ASTG;
        const int kpos = it >> 2;
        const int cchunk = (it & 3) * 8;     // 16B-chunk base of ci block
        const int woff = 59 + (kpos / 3) * PROW + (kpos % 3) - (PROW + 1);

        #pragma unroll
        for (int kk = 0; kk < 4; kk++) {
            uint32_t a[4][4];
            #pragma unroll
            for (int im = 0; im < 4; im++) {
                uint32_t byte = (wm * 64 + im * 16 + a_row) * 128 +
                                (kk * 16 + a_kh) * 2;
                ldmx4(a[im], as + SWZ(byte));
            }
            uint32_t bf[2][4];
            #pragma unroll
            for (int j = 0; j < 2; j++) {
                int wrow = woff + wn * 32 + j * 16 + b_row;
                int ck   = cchunk + kk * 2 + b_ck;
                ldmx4(bf[j], bw + wrow * 512 +
                             (((uint32_t)(ck ^ (wrow & 7))) << 4));
            }
            #pragma unroll
            for (int im = 0; im < 4; im++)
                #pragma unroll
                for (int in = 0; in < 4; in++)
                    mma16816(d[im][in], a[im],
                             bf[in >> 1][(in & 1) * 2],
                             bf[in >> 1][(in & 1) * 2 + 1]);
        }
        __syncthreads();
    }

    // ---- epilogue: BN + SiLU + masked store ----
    const int t4 = lane >> 2, tp = lane & 3;
    #pragma unroll
    for (int im = 0; im < 4; im++) {
        int mloc = wm * 64 + im * 16 + t4;
        #pragma unroll
        for (int h = 0; h < 2; h++) {
            int oc = mloc + h * 8;
            float inv = bn_gamma[oc] * rsqrtf(bn_var[oc] + 1e-5f);
            float bia = bn_beta[oc] - bn_mean[oc] * inv;
            float* ob = out + (size_t)(b * COUT + oc) * HWSZ;
            #pragma unroll
            for (int in = 0; in < 4; in++) {
                int pbase = p0 + wn * 32 + in * 8 + tp * 2;
                #pragma unroll
                for (int e = 0; e < 2; e++) {
                    int p = pbase + e;
                    int rr = p / PROW - 1, ww = p % PROW - 1;
                    if (rr >= 0 && rr < HH && ww >= 0 && ww < WW) {
                        float z = d[im][in][h * 2 + e] * inv + bia;
                        ob[rr * WW + ww] = z / (1.f + __expf(-z));
                    }
                }
            }
        }
    }
}

// ---------------------------------------------------------------------------
extern "C" void kernel_launch(void* const* d_in, const int* in_sizes, int n_in,
                              void* d_out, int out_size) {
    const float* x         = (const float*)d_in[0];
    const float* routing_w = (const float*)d_in[1];
    const float* routing_b = (const float*)d_in[2];
    const float* kernel_w  = (const float*)d_in[3];
    const float* bn_gamma  = (const float*)d_in[4];
    const float* bn_beta   = (const float*)d_in[5];
    const float* bn_mean   = (const float*)d_in[6];
    const float* bn_var    = (const float*)d_in[7];
    float* out = (float*)d_out;

    cudaFuncSetAttribute(conv_hmma_kernel,
                         cudaFuncAttributeMaxDynamicSharedMemorySize, SMEM_DYN);

    pool_kernel<<<BATCH * CIN, 128>>>(x);
    route_kernel<<<1, 128>>>(routing_w, routing_b);
    combine_kernel<<<COUT, 256>>>(kernel_w);
    prep_kernel<<<dim3(PTOT / 64, CIN / 64, BATCH), 256>>>(x);

    dim3 grid(NT, BATCH);
    conv_hmma_kernel<<<grid, 512, SMEM_DYN>>>(bn_gamma, bn_beta, bn_mean,
                                              bn_var, out);
}